// round 15
// baseline (speedup 1.0000x reference)
#include <cuda_runtime.h>
#include <cuda_bf16.h>
#include <cstdint>

#define Hdim 128
#define KSUB 16
#define SK_C 128000
#define N_C  60000
#define S_C  8000
#define L_C  3
#define EI_C 512000
#define EG_C 960000
#define HH   (Hdim * Hdim)

#define FLAG_RELU    1
#define FLAG_ACCUM   2
#define FLAG_PACKOUT 4
#define FLAG_COMBINE 8

#define CDIV(a, b) (((a) + (b) - 1) / (b))

// ------------------------- scratch -------------------------
__device__ float g_h[SK_C * Hdim];      // packed bf16 hi|lo
__device__ float g_acc[SK_C * Hdim];
__device__ float g_tmp[SK_C * Hdim];    // packed
__device__ float g_xsum[N_C * Hdim];
__device__ float g_tmpN[N_C * Hdim];    // packed
__device__ float g_yvv[N_C * Hdim];
__device__ float g_xvvc[N_C * Hdim];
__device__ float g_ykk[S_C * Hdim];
__device__ int   g_cnt[N_C];
__device__ int   g_rcnt[N_C];
__device__ unsigned char g_wbf[L_C * 7 * 65536];

// CSR scratch
__device__ int g_irp[SK_C + 1];
__device__ int g_ipk[EI_C];
__device__ int g_ideg[SK_C];
__device__ int g_ibs[512];
__device__ int g_grp[N_C + 1];
__device__ int g_gpk[EG_C];
__device__ int g_gdeg[N_C];
__device__ int g_gbs[512];

// ------------------------- helpers -------------------------
__device__ __forceinline__ uint32_t smem_u32(const void* p) {
    uint32_t a;
    asm("{ .reg .u64 t; cvta.to.shared.u64 t, %1; cvt.u32.u64 %0, t; }" : "=r"(a) : "l"(p));
    return a;
}
__device__ __forceinline__ void ldsm4(uint32_t* r, uint32_t addr) {
    asm volatile("ldmatrix.sync.aligned.m8n8.x4.shared.b16 {%0,%1,%2,%3}, [%4];"
        : "=r"(r[0]), "=r"(r[1]), "=r"(r[2]), "=r"(r[3]) : "r"(addr));
}
__device__ __forceinline__ void mma16816(float* c, const uint32_t* a, uint32_t b0, uint32_t b1) {
    asm volatile("mma.sync.aligned.m16n8k16.row.col.f32.bf16.bf16.f32 "
        "{%0,%1,%2,%3}, {%4,%5,%6,%7}, {%8,%9}, {%0,%1,%2,%3};"
        : "+f"(c[0]), "+f"(c[1]), "+f"(c[2]), "+f"(c[3])
        : "r"(a[0]), "r"(a[1]), "r"(a[2]), "r"(a[3]), "r"(b0), "r"(b1));
}
__device__ __forceinline__ uint32_t pack_bf16(float x, float y) {
    __nv_bfloat162 h = __float22bfloat162_rn(make_float2(x, y));
    return *(uint32_t*)&h;
}
__device__ __forceinline__ uint32_t split_pack(float x) {
    __nv_bfloat16 hb = __float2bfloat16_rn(x);
    float hf = __bfloat162float(hb);
    __nv_bfloat16 lb = __float2bfloat16_rn(x - hf);
    return (uint32_t)__bfloat16_as_ushort(hb) | ((uint32_t)__bfloat16_as_ushort(lb) << 16);
}
__device__ __forceinline__ float rec_pk(uint32_t p) {
    return __uint_as_float(p << 16) + __uint_as_float(p & 0xFFFF0000u);
}
__device__ __forceinline__ void red_v4(float* p, float x, float y, float z, float w) {
    asm volatile("red.global.add.v4.f32 [%0], {%1, %2, %3, %4};"
        :: "l"(p), "f"(x), "f"(y), "f"(z), "f"(w) : "memory");
}
__device__ __forceinline__ void red_v2(float* p, float x, float y) {
    asm volatile("red.global.add.v2.f32 [%0], {%1, %2};"
        :: "l"(p), "f"(x), "f"(y) : "memory");
}

// ------------------------- weight prep -------------------------
__global__ void prep_weights(const float* __restrict__ s0, const float* __restrict__ s1,
                             const float* __restrict__ s2, const float* __restrict__ s3,
                             const float* __restrict__ s4, const float* __restrict__ s5,
                             const float* __restrict__ s6, unsigned char* __restrict__ dst, int L)
{
    int i = blockIdx.x * blockDim.x + threadIdx.x;
    int total = L * 7 * HH;
    if (i >= total) return;
    int m = i >> 14;
    int r = i & (HH - 1);
    int o = r >> 7, k = r & 127;
    int l = m / 7, j = m % 7;
    const float* base;
    switch (j) {
        case 0: base = s0; break;
        case 1: base = s1; break;
        case 2: base = s2; break;
        case 3: base = s3; break;
        case 4: base = s4; break;
        case 5: base = s5; break;
        default: base = s6; break;
    }
    float v = base[(size_t)l * HH + o * Hdim + k];
    __nv_bfloat16 hb = __float2bfloat16_rn(v);
    float lo = v - __bfloat162float(hb);
    __nv_bfloat16 lb = __float2bfloat16_rn(lo);
    uint32_t off = (uint32_t)(o * 256 + (((k >> 3) ^ (o & 7)) * 16) + (k & 7) * 2);
    unsigned char* mb = dst + (size_t)m * 65536;
    *(unsigned short*)(mb + off)          = __bfloat16_as_ushort(hb);
    *(unsigned short*)(mb + 32768 + off)  = __bfloat16_as_ushort(lb);
}

// ------------------------- CSR build -------------------------
__global__ void hist_kernel(const int* __restrict__ dst, int* __restrict__ deg, int E)
{
    int e = blockIdx.x * blockDim.x + threadIdx.x;
    if (e < E) atomicAdd(&deg[dst[e]], 1);
}

__global__ void scan_part(const int* __restrict__ deg, int* __restrict__ rowptr,
                          int* __restrict__ bsum, int n)
{
    __shared__ int s[256];
    int i = blockIdx.x * 256 + threadIdx.x;
    int v = (i < n) ? deg[i] : 0;
    s[threadIdx.x] = v;
    __syncthreads();
#pragma unroll
    for (int off = 1; off < 256; off <<= 1) {
        int t = (threadIdx.x >= off) ? s[threadIdx.x - off] : 0;
        __syncthreads();
        s[threadIdx.x] += t;
        __syncthreads();
    }
    if (i < n) rowptr[i] = s[threadIdx.x] - v;
    if (threadIdx.x == 255) bsum[blockIdx.x] = s[255];
}

__global__ void scan_top(int* __restrict__ bsum, int B)
{
    __shared__ int s[512];
    int v = (threadIdx.x < B) ? bsum[threadIdx.x] : 0;
    s[threadIdx.x] = v;
    __syncthreads();
#pragma unroll
    for (int off = 1; off < 512; off <<= 1) {
        int t = (threadIdx.x >= off) ? s[threadIdx.x - off] : 0;
        __syncthreads();
        s[threadIdx.x] += t;
        __syncthreads();
    }
    if (threadIdx.x < B) bsum[threadIdx.x] = s[threadIdx.x] - v;
}

__global__ void scan_add(int* __restrict__ rowptr, const int* __restrict__ bsum, int n, int E)
{
    int i = blockIdx.x * blockDim.x + threadIdx.x;
    if (i < n) rowptr[i] += bsum[i >> 8];
    if (i == n) rowptr[n] = E;
}

__global__ void csr_scatter(const int* __restrict__ src, const int* __restrict__ dst,
                            const int* __restrict__ bid, int* __restrict__ cursor,
                            int* __restrict__ packed, int E)
{
    int e = blockIdx.x * blockDim.x + threadIdx.x;
    if (e >= E) return;
    int d = dst[e];
    int pos = atomicAdd(&cursor[d], 1);
    packed[pos] = src[e] | (bid[e] << 25);
}

// ------------------------- tensor-core GEMM (+gather A-load, +combine epilogue) -------------------------
// gmode: 0 = plain A-load ; 1 = packed X1 + CSR gather (no cnt) ; 2 = fp32 X1 + cnt scaling + CSR gather
#define SMEM_DYN 196608

__global__ __launch_bounds__(512)
void gemm_mma(const float* __restrict__ X1, const int* __restrict__ rowScale,
              const unsigned char* __restrict__ WB, const float* __restrict__ bias,
              const float* __restrict__ gamma, const float* __restrict__ beta,
              const float* __restrict__ accIn, const float* __restrict__ yvv,
              const float* __restrict__ ykk,
              const int* __restrict__ node_ids, const int* __restrict__ sub_batch,
              float* __restrict__ xsum, float* __restrict__ xvvc,
              const int* __restrict__ rowptr, const int* __restrict__ epk,
              const float* __restrict__ bond,
              float* __restrict__ Y, int M, long inStride, int flags, int inFmt, int gmode)
{
    extern __shared__ char sm[];
    const uint32_t sbase = smem_u32(sm);
    const int tid = threadIdx.x;
    const long m0 = (long)blockIdx.x * 256;

    {
        const float4* wsrc = (const float4*)WB;
        float4* wdst = (float4*)(sm + 131072);
#pragma unroll
        for (int i = 0; i < 8; i++)
            wdst[tid + i * 512] = wsrc[tid + i * 512];
    }

    if (gmode != 0) {
        // gather A-load: v = own + sum_e relu(src*inv + bond)
#pragma unroll 1
        for (int i = 0; i < 8; i++) {
            int g = tid + i * 512;
            int row = g >> 4, chunk = g & 15;
            long m = m0 + row;
            float v[8];
#pragma unroll
            for (int q = 0; q < 8; q++) v[q] = 0.f;
            if (m < M) {
                if (gmode == 1) {
                    const uint4* xp = (const uint4*)((const uint32_t*)X1 + m * (long)Hdim + chunk * 8);
                    uint4 pa = xp[0], pb = xp[1];
                    v[0] = rec_pk(pa.x); v[1] = rec_pk(pa.y);
                    v[2] = rec_pk(pa.z); v[3] = rec_pk(pa.w);
                    v[4] = rec_pk(pb.x); v[5] = rec_pk(pb.y);
                    v[6] = rec_pk(pb.z); v[7] = rec_pk(pb.w);
                } else {
                    const float* xp = X1 + m * (long)Hdim + chunk * 8;
                    float4 a = *(const float4*)xp;
                    float4 b = *(const float4*)(xp + 4);
                    float invw = 1.f / (float)max(__ldg(rowScale + m), 1);
                    v[0] = a.x * invw; v[1] = a.y * invw; v[2] = a.z * invw; v[3] = a.w * invw;
                    v[4] = b.x * invw; v[5] = b.y * invw; v[6] = b.z * invw; v[7] = b.w * invw;
                }
                int beg = __ldg(rowptr + m), end = __ldg(rowptr + m + 1);
                for (int e = beg; e < end; e++) {
                    uint32_t p = (uint32_t)__ldg(epk + e);
                    int s = (int)(p & 0x1FFFFFFu);
                    int b = (int)(p >> 25);
                    const float* bp = bond + (size_t)b * Hdim + chunk * 8;
                    float4 b0 = *(const float4*)bp;
                    float4 b1 = *(const float4*)(bp + 4);
                    float sv[8];
                    float inv = 1.f;
                    if (gmode == 1) {
                        const uint4* sp = (const uint4*)((const uint32_t*)X1 + (size_t)s * Hdim + chunk * 8);
                        uint4 qa = sp[0], qb = sp[1];
                        sv[0] = rec_pk(qa.x); sv[1] = rec_pk(qa.y);
                        sv[2] = rec_pk(qa.z); sv[3] = rec_pk(qa.w);
                        sv[4] = rec_pk(qb.x); sv[5] = rec_pk(qb.y);
                        sv[6] = rec_pk(qb.z); sv[7] = rec_pk(qb.w);
                    } else {
                        const float* sp = X1 + (size_t)s * Hdim + chunk * 8;
                        float4 qa = *(const float4*)sp;
                        float4 qb = *(const float4*)(sp + 4);
                        sv[0] = qa.x; sv[1] = qa.y; sv[2] = qa.z; sv[3] = qa.w;
                        sv[4] = qb.x; sv[5] = qb.y; sv[6] = qb.z; sv[7] = qb.w;
                        inv = 1.f / (float)max(__ldg(rowScale + s), 1);
                    }
                    v[0] += fmaxf(sv[0] * inv + b0.x, 0.f);
                    v[1] += fmaxf(sv[1] * inv + b0.y, 0.f);
                    v[2] += fmaxf(sv[2] * inv + b0.z, 0.f);
                    v[3] += fmaxf(sv[3] * inv + b0.w, 0.f);
                    v[4] += fmaxf(sv[4] * inv + b1.x, 0.f);
                    v[5] += fmaxf(sv[5] * inv + b1.y, 0.f);
                    v[6] += fmaxf(sv[6] * inv + b1.z, 0.f);
                    v[7] += fmaxf(sv[7] * inv + b1.w, 0.f);
                }
            }
            uint32_t hp[4], lp[4];
#pragma unroll
            for (int q = 0; q < 4; q++) {
                float x = v[q * 2], y = v[q * 2 + 1];
                uint32_t hh = pack_bf16(x, y);
                __nv_bfloat162 hv = *(__nv_bfloat162*)&hh;
                hp[q] = hh;
                lp[q] = pack_bf16(x - __bfloat162float(hv.x), y - __bfloat162float(hv.y));
            }
            uint32_t off = (uint32_t)(row * 256 + ((chunk ^ (row & 7)) * 16));
            *(uint4*)(sm + off)         = make_uint4(hp[0], hp[1], hp[2], hp[3]);
            *(uint4*)(sm + 65536 + off) = make_uint4(lp[0], lp[1], lp[2], lp[3]);
        }
    } else if (inFmt) {
        // fast path: X1 already packed bf16 hi|lo
#pragma unroll
        for (int i = 0; i < 8; i++) {
            int g = tid + i * 512;
            int row = g >> 4, chunk = g & 15;
            long m = m0 + row;
            uint4 pa = make_uint4(0, 0, 0, 0), pb = make_uint4(0, 0, 0, 0);
            if (m < M) {
                const uint4* xp = (const uint4*)((const uint32_t*)X1 + m * inStride + chunk * 8);
                pa = xp[0];
                pb = xp[1];
            }
            uint4 hi, lo;
            hi.x = __byte_perm(pa.x, pa.y, 0x5410);
            hi.y = __byte_perm(pa.z, pa.w, 0x5410);
            hi.z = __byte_perm(pb.x, pb.y, 0x5410);
            hi.w = __byte_perm(pb.z, pb.w, 0x5410);
            lo.x = __byte_perm(pa.x, pa.y, 0x7632);
            lo.y = __byte_perm(pa.z, pa.w, 0x7632);
            lo.z = __byte_perm(pb.x, pb.y, 0x7632);
            lo.w = __byte_perm(pb.z, pb.w, 0x7632);
            uint32_t off = (uint32_t)(row * 256 + ((chunk ^ (row & 7)) * 16));
            *(uint4*)(sm + off)         = hi;
            *(uint4*)(sm + 65536 + off) = lo;
        }
    } else {
        // fp32 A-load (+optional rowScale)
#pragma unroll
        for (int i = 0; i < 8; i++) {
            int g = tid + i * 512;
            int row = g >> 4, chunk = g & 15;
            long m = m0 + row;
            float v[8];
#pragma unroll
            for (int q = 0; q < 8; q++) v[q] = 0.f;
            if (m < M) {
                const float* xp = X1 + m * inStride + chunk * 8;
                float4 a = *(const float4*)xp;
                float4 b = *(const float4*)(xp + 4);
                v[0] = a.x; v[1] = a.y; v[2] = a.z; v[3] = a.w;
                v[4] = b.x; v[5] = b.y; v[6] = b.z; v[7] = b.w;
                if (rowScale) {
                    float inv = 1.f / (float)max(__ldg(rowScale + m), 1);
#pragma unroll
                    for (int q = 0; q < 8; q++) v[q] *= inv;
                }
            }
            uint32_t hp[4], lp[4];
#pragma unroll
            for (int q = 0; q < 4; q++) {
                float x = v[q * 2], y = v[q * 2 + 1];
                uint32_t hh = pack_bf16(x, y);
                __nv_bfloat162 hv = *(__nv_bfloat162*)&hh;
                hp[q] = hh;
                lp[q] = pack_bf16(x - __bfloat162float(hv.x), y - __bfloat162float(hv.y));
            }
            uint32_t off = (uint32_t)(row * 256 + ((chunk ^ (row & 7)) * 16));
            *(uint4*)(sm + off)         = make_uint4(hp[0], hp[1], hp[2], hp[3]);
            *(uint4*)(sm + 65536 + off) = make_uint4(lp[0], lp[1], lp[2], lp[3]);
        }
    }
    __syncthreads();

    const int wid = tid >> 5, lane = tid & 31;
    const int rw = (wid & 7) * 32;
    const int cw = (wid >> 3) * 64;
    const int lg = lane >> 3, lr = lane & 7;

    float c[2][8][4];
#pragma unroll
    for (int mt = 0; mt < 2; mt++)
#pragma unroll
        for (int nt = 0; nt < 8; nt++)
#pragma unroll
            for (int q = 0; q < 4; q++) c[mt][nt][q] = 0.f;

    const int aRow0 = rw + (lg & 1) * 8 + lr;
    const int bN0   = cw + (lg >> 1) * 8 + lr;

#pragma unroll 1
    for (int ks = 0; ks < 8; ks++) {
        const int kcA = ks * 2 + (lg >> 1);
        const int kcB = ks * 2 + (lg & 1);
        uint32_t ah[2][4], al[2][4];
#pragma unroll
        for (int mt = 0; mt < 2; mt++) {
            int row = aRow0 + mt * 16;
            uint32_t addr = sbase + row * 256 + ((kcA ^ (row & 7)) * 16);
            ldsm4(ah[mt], addr);
            ldsm4(al[mt], addr + 65536);
        }
#pragma unroll
        for (int ng = 0; ng < 4; ng++) {
            int n = bN0 + ng * 16;
            uint32_t baddr = sbase + 131072 + n * 256 + ((kcB ^ (n & 7)) * 16);
            uint32_t bh[4], bl[4];
            ldsm4(bh, baddr);
            ldsm4(bl, baddr + 32768);
#pragma unroll
            for (int mt = 0; mt < 2; mt++) {
#pragma unroll
                for (int half = 0; half < 2; half++) {
                    int nt = ng * 2 + half;
                    mma16816(c[mt][nt], ah[mt], bh[half * 2], bh[half * 2 + 1]);
                    mma16816(c[mt][nt], ah[mt], bl[half * 2], bl[half * 2 + 1]);
                    mma16816(c[mt][nt], al[mt], bh[half * 2], bh[half * 2 + 1]);
                }
            }
        }
    }

    {
        const int ncol0 = cw + (lane & 3) * 2;
        float2 bi[8], ga[8], be[8];
#pragma unroll
        for (int nt = 0; nt < 8; nt++) {
            bi[nt] = *(const float2*)(bias + ncol0 + nt * 8);
            if (gamma) {
                ga[nt] = *(const float2*)(gamma + ncol0 + nt * 8);
                be[nt] = *(const float2*)(beta  + ncol0 + nt * 8);
            }
        }
#pragma unroll
        for (int mt = 0; mt < 2; mt++) {
#pragma unroll
            for (int h = 0; h < 2; h++) {
                long m = m0 + rw + mt * 16 + h * 8 + (lane >> 2);
                if (m >= M) continue;
                if (flags & FLAG_COMBINE) {
                    uint32_t* hrow = (uint32_t*)Y + m * (long)Hdim;
                    int nid = __ldg(node_ids + m);
                    if (nid < 0) {
#pragma unroll
                        for (int nt = 0; nt < 8; nt++)
                            *(uint2*)(hrow + ncol0 + nt * 8) = make_uint2(0u, 0u);
                    } else {
                        int sb = __ldg(sub_batch + m);
                        const float* arow = accIn + m * (long)Hdim;
                        const float* vrow = yvv + (size_t)nid * Hdim;
                        const float* krow = ykk + (size_t)sb * Hdim;
                        float* xsrow = xsum + (size_t)nid * Hdim;
                        float* xvrow = xvvc + (size_t)nid * Hdim;
                        bool isRoot = ((m & (KSUB - 1)) == 0);
#pragma unroll
                        for (int nt = 0; nt < 8; nt++) {
                            int col = ncol0 + nt * 8;
                            float x = c[mt][nt][h * 2 + 0] + bi[nt].x;
                            float y = c[mt][nt][h * 2 + 1] + bi[nt].y;
                            x = x * ga[nt].x + be[nt].x;
                            y = y * ga[nt].y + be[nt].y;
                            float2 av = *(const float2*)(arow + col);
                            float2 vv = *(const float2*)(vrow + col);
                            float2 kv = *(const float2*)(krow + col);
                            x = fmaxf(x + av.x + vv.x + kv.x, 0.f);
                            y = fmaxf(y + av.y + vv.y + kv.y, 0.f);
                            *(uint2*)(hrow + col) = make_uint2(split_pack(x), split_pack(y));
                            red_v2(xsrow + col, x, y);
                            if (isRoot) red_v2(xvrow + col, x, y);
                        }
                    }
                } else {
                    float* yrow = Y + m * (long)Hdim;
#pragma unroll
                    for (int nt = 0; nt < 8; nt++) {
                        int col = ncol0 + nt * 8;
                        float x = c[mt][nt][h * 2 + 0] + bi[nt].x;
                        float y = c[mt][nt][h * 2 + 1] + bi[nt].y;
                        if (gamma) {
                            x = x * ga[nt].x + be[nt].x;
                            y = y * ga[nt].y + be[nt].y;
                        }
                        if (flags & FLAG_RELU) { x = fmaxf(x, 0.f); y = fmaxf(y, 0.f); }
                        if (flags & FLAG_ACCUM) {
                            float2 old = *(float2*)(yrow + col);
                            x += old.x; y += old.y;
                        }
                        if (flags & FLAG_PACKOUT) {
                            uint2 pk = make_uint2(split_pack(x), split_pack(y));
                            *(uint2*)((uint32_t*)yrow + col) = pk;
                        } else {
                            *(float2*)(yrow + col) = make_float2(x, y);
                        }
                    }
                }
            }
        }
    }
}

// ------------------------- counts -------------------------
__global__ void count_kernel(const int* __restrict__ node_ids, int* __restrict__ cnt, int SKn)
{
    int i = blockIdx.x * blockDim.x + threadIdx.x;
    if (i >= SKn) return;
    int nid = node_ids[i];
    if (nid >= 0) atomicAdd(&cnt[nid], 1);
}
__global__ void rcount_kernel(const int* __restrict__ node_ids, int* __restrict__ rcnt, int Sn)
{
    int s = blockIdx.x * blockDim.x + threadIdx.x;
    if (s >= Sn) return;
    int nid = node_ids[s * KSUB];
    if (nid >= 0) atomicAdd(&rcnt[nid], 1);
}

// ------------------------- init h -------------------------
__global__ void init_h(const float* __restrict__ atom_table, const float* __restrict__ role_table,
                       const int* __restrict__ atom_ids, const int* __restrict__ node_ids,
                       float* __restrict__ h, float* __restrict__ xsum, float* __restrict__ xvvc,
                       int SKn)
{
    int t = blockIdx.x * blockDim.x + threadIdx.x;
    int row = t >> 5;
    if (row >= SKn) return;
    int q = t & 31;
    int nid = node_ids[row];
    float4 out = make_float4(0.f, 0.f, 0.f, 0.f);
    if (nid >= 0) {
        int aid = atom_ids[row];
        float4 v = *(const float4*)(atom_table + (size_t)aid * Hdim + q * 4);
        const float* role = role_table + (((row & (KSUB - 1)) == 0) ? Hdim : 0);
        float4 r = *(const float4*)(role + q * 4);
        out = make_float4(v.x + r.x, v.y + r.y, v.z + r.z, v.w + r.w);
    }
    uint4 pk = make_uint4(split_pack(out.x), split_pack(out.y),
                          split_pack(out.z), split_pack(out.w));
    *(uint4*)((uint32_t*)h + (size_t)row * Hdim + q * 4) = pk;
    if (nid >= 0) {
        red_v4(xsum + (size_t)nid * Hdim + q * 4, out.x, out.y, out.z, out.w);
        if ((row & (KSUB - 1)) == 0)
            red_v4(xvvc + (size_t)nid * Hdim + q * 4, out.x, out.y, out.z, out.w);
    }
}

// ------------------------- final pool -------------------------
__global__ void pool_kernel(const float* __restrict__ xsum, const int* __restrict__ cnt,
                            const int* __restrict__ batch, float* __restrict__ out, int Nn)
{
    int t = blockIdx.x * blockDim.x + threadIdx.x;
    int n = t >> 5;
    if (n >= Nn) return;
    int q = t & 31;
    float inv = 1.f / (float)max(cnt[n], 1);
    int g = batch[n];
    float4 v = *(const float4*)(xsum + (size_t)n * Hdim + q * 4);
    red_v4(out + (size_t)g * Hdim + q * 4, v.x * inv, v.y * inv, v.z * inv, v.w * inv);
}

// ------------------------- host orchestration -------------------------
extern "C" void kernel_launch(void* const* d_in, const int* in_sizes, int n_in,
                              void* d_out, int out_size)
{
    const float* atom_table = (const float*)d_in[0];
    const float* bond_table = (const float*)d_in[1];
    const float* role_table = (const float*)d_in[2];
    const float* lW1  = (const float*)d_in[3];
    const float* lb1  = (const float*)d_in[4];
    const float* lW2  = (const float*)d_in[5];
    const float* lb2  = (const float*)d_in[6];
    const float* gW1  = (const float*)d_in[7];
    const float* gb1  = (const float*)d_in[8];
    const float* gW2  = (const float*)d_in[9];
    const float* gb2  = (const float*)d_in[10];
    const float* lbn_g = (const float*)d_in[11];
    const float* lbn_b = (const float*)d_in[12];
    const float* gbn_g = (const float*)d_in[13];
    const float* gbn_b = (const float*)d_in[14];
    const float* skipW = (const float*)d_in[15];
    const float* skipb = (const float*)d_in[16];
    const float* vvW  = (const float*)d_in[17];
    const float* vvb  = (const float*)d_in[18];
    const float* kkW  = (const float*)d_in[19];
    const float* kkb  = (const float*)d_in[20];
    const int* atom_ids  = (const int*)d_in[21];
    const int* bid_i     = (const int*)d_in[22];
    const int* bid_g     = (const int*)d_in[23];
    const int* intra_ei  = (const int*)d_in[24];
    const int* node_ids  = (const int*)d_in[25];
    const int* edge_index = (const int*)d_in[26];
    const int* sub_batch = (const int*)d_in[27];
    const int* batch     = (const int*)d_in[28];

    const int SKn = in_sizes[21];
    const int EIn = in_sizes[22];
    const int EGn = in_sizes[23];
    const int Nn  = in_sizes[28];
    const int Sn  = SKn / KSUB;
    const int L   = in_sizes[4] / Hdim;

    float *h, *acc, *tmp, *xsum, *tmpN, *yvv, *xvvc, *ykk;
    int *cnt, *rcnt;
    int *irp, *ipk, *ideg, *ibs, *grp, *gpk, *gdeg, *gbs;
    unsigned char* wbf;
    cudaGetSymbolAddress((void**)&h,    g_h);
    cudaGetSymbolAddress((void**)&acc,  g_acc);
    cudaGetSymbolAddress((void**)&tmp,  g_tmp);
    cudaGetSymbolAddress((void**)&xsum, g_xsum);
    cudaGetSymbolAddress((void**)&tmpN, g_tmpN);
    cudaGetSymbolAddress((void**)&yvv,  g_yvv);
    cudaGetSymbolAddress((void**)&xvvc, g_xvvc);
    cudaGetSymbolAddress((void**)&ykk,  g_ykk);
    cudaGetSymbolAddress((void**)&cnt,  g_cnt);
    cudaGetSymbolAddress((void**)&rcnt, g_rcnt);
    cudaGetSymbolAddress((void**)&wbf,  g_wbf);
    cudaGetSymbolAddress((void**)&irp,  g_irp);
    cudaGetSymbolAddress((void**)&ipk,  g_ipk);
    cudaGetSymbolAddress((void**)&ideg, g_ideg);
    cudaGetSymbolAddress((void**)&ibs,  g_ibs);
    cudaGetSymbolAddress((void**)&grp,  g_grp);
    cudaGetSymbolAddress((void**)&gpk,  g_gpk);
    cudaGetSymbolAddress((void**)&gdeg, g_gdeg);
    cudaGetSymbolAddress((void**)&gbs,  g_gbs);

    cudaFuncSetAttribute(gemm_mma, cudaFuncAttributeMaxDynamicSharedMemorySize, SMEM_DYN);

    static cudaStream_t st1 = nullptr, st2 = nullptr;
    static cudaEvent_t ev[24];
    if (!st1) {
        cudaStreamCreateWithFlags(&st1, cudaStreamNonBlocking);
        cudaStreamCreateWithFlags(&st2, cudaStreamNonBlocking);
        for (int i = 0; i < 24; i++)
            cudaEventCreateWithFlags(&ev[i], cudaEventDisableTiming);
    }

    const int TB = 256;
    const size_t nBytes = (size_t)Nn * Hdim * sizeof(float);

#define GEMM_FULL(stream, X1p, rsp, widx, biasp, gammap, betap, accp, yvvp, ykkp, nidp, sbp, xsp, xvp, rpp, epp, bondp, Yp, Mv, strv, flg, fmt, gm) \
    gemm_mma<<<CDIV((Mv), 256), 512, SMEM_DYN, (stream)>>>((X1p), (rsp), \
        wbf + (size_t)(widx) * 65536, (biasp), (gammap), (betap), (accp), (yvvp), (ykkp), \
        (nidp), (sbp), (xsp), (xvp), (rpp), (epp), (bondp), (Yp), (Mv), (strv), (flg), (fmt), (gm))
#define GEMM_S(stream, X1p, rsp, widx, biasp, gammap, betap, Yp, Mv, strv, flg, fmt) \
    GEMM_FULL(stream, X1p, rsp, widx, biasp, gammap, betap, nullptr, nullptr, nullptr, \
           nullptr, nullptr, nullptr, nullptr, nullptr, nullptr, nullptr, Yp, Mv, strv, flg, fmt, 0)

    // ---- fork FIRST ----
    cudaEvent_t eStart = ev[22];
    cudaEventRecord(eStart, 0);
    cudaStreamWaitEvent(st1, eStart, 0);
    cudaStreamWaitEvent(st2, eStart, 0);

    // st1: intra CSR
    {
        int B = CDIV(SKn, 256);
        cudaMemsetAsync(ideg, 0, (size_t)SKn * sizeof(int), st1);
        hist_kernel<<<CDIV(EIn, TB), TB, 0, st1>>>(intra_ei + EIn, ideg, EIn);
        scan_part<<<B, 256, 0, st1>>>(ideg, irp, ibs, SKn);
        scan_top<<<1, 512, 0, st1>>>(ibs, B);
        scan_add<<<CDIV(SKn + 1, TB), TB, 0, st1>>>(irp, ibs, SKn, EIn);
        cudaMemcpyAsync(ideg, irp, (size_t)SKn * sizeof(int), cudaMemcpyDeviceToDevice, st1);
        csr_scatter<<<CDIV(EIn, TB), TB, 0, st1>>>(intra_ei, intra_ei + EIn, bid_i, ideg, ipk, EIn);
    }
    // st2: global CSR
    {
        int B = CDIV(Nn, 256);
        cudaMemsetAsync(gdeg, 0, (size_t)Nn * sizeof(int), st2);
        hist_kernel<<<CDIV(EGn, TB), TB, 0, st2>>>(edge_index + EGn, gdeg, EGn);
        scan_part<<<B, 256, 0, st2>>>(gdeg, grp, gbs, Nn);
        scan_top<<<1, 512, 0, st2>>>(gbs, B);
        scan_add<<<CDIV(Nn + 1, TB), TB, 0, st2>>>(grp, gbs, Nn, EGn);
        cudaMemcpyAsync(gdeg, grp, (size_t)Nn * sizeof(int), cudaMemcpyDeviceToDevice, st2);
        csr_scatter<<<CDIV(EGn, TB), TB, 0, st2>>>(edge_index, edge_index + EGn, bid_g, gdeg, gpk, EGn);
    }
    cudaEvent_t eCsr2 = ev[23];
    cudaEventRecord(eCsr2, st2);
    cudaStreamWaitEvent(0, eCsr2, 0);

    // stream 0: weights, counts, init
    prep_weights<<<CDIV(L * 7 * HH, TB), TB>>>(skipW, lW1, lW2, gW1, gW2, vvW, kkW, wbf, L);
    cudaMemsetAsync(cnt,  0, (size_t)Nn * sizeof(int));
    cudaMemsetAsync(rcnt, 0, (size_t)Nn * sizeof(int));
    count_kernel<<<CDIV(SKn, TB), TB>>>(node_ids, cnt, SKn);
    rcount_kernel<<<CDIV(Sn, TB), TB>>>(node_ids, rcnt, Sn);
    cudaMemsetAsync(xsum, 0, nBytes);
    cudaMemsetAsync(xvvc, 0, nBytes);
    init_h<<<CDIV(SKn * 32, TB), TB>>>(atom_table, role_table, atom_ids, node_ids,
                                       h, xsum, xvvc, SKn);

    for (int l = 0; l < L; l++) {
        const int w0 = l * 7;
        cudaEvent_t eFork = ev[l * 7 + 0];
        cudaEvent_t eS1   = ev[l * 7 + 1];
        cudaEvent_t eS2   = ev[l * 7 + 2];
        cudaEvent_t eVV   = ev[l * 7 + 3];
        cudaEvent_t eG1   = ev[l * 7 + 4];
        cudaEvent_t eG2   = ev[l * 7 + 5];

        cudaEventRecord(eFork, 0);
        cudaStreamWaitEvent(st1, eFork, 0);
        cudaStreamWaitEvent(st2, eFork, 0);

        // ---- st2 (part 1): skip -> acc ; vv -> yvv ; kk -> ykk ----
        GEMM_S(st2, h, nullptr, w0 + 0, skipb + l * Hdim,
               nullptr, nullptr, acc, SKn, (long)Hdim, 0, 1);
        GEMM_S(st2, xvvc, rcnt, w0 + 5, vvb + l * Hdim,
               nullptr, nullptr, yvv, Nn, (long)Hdim, 0, 0);
        cudaEventRecord(eVV, st2);
        GEMM_S(st2, h, nullptr, w0 + 6, kkb + l * Hdim,
               nullptr, nullptr, ykk, Sn, (long)KSUB * Hdim, 0, 1);

        // ---- stream 0: g1 (fused global gather) ----
        GEMM_FULL(0, xsum, cnt, w0 + 3, gb1 + l * Hdim, nullptr, nullptr,
                  nullptr, nullptr, nullptr, nullptr, nullptr, nullptr, nullptr,
                  grp, gpk, bond_table,
                  tmpN, Nn, (long)Hdim, FLAG_RELU | FLAG_PACKOUT, 0, 2);
        cudaEventRecord(eG1, 0);

        // ---- st2 (part 2): memsets after g1 consumed xsum ----
        cudaStreamWaitEvent(st2, eG1, 0);
        cudaMemsetAsync(xsum, 0, nBytes, st2);
        cudaMemsetAsync(xvvc, 0, nBytes, st2);
        cudaEventRecord(eS2, st2);

        // ---- stream 0: g2 (accum into yvv) ----
        cudaStreamWaitEvent(0, eVV, 0);
        GEMM_S(0, tmpN, nullptr, w0 + 4, gb2 + l * Hdim,
               gbn_g + l * Hdim, gbn_b + l * Hdim, yvv, Nn, (long)Hdim, FLAG_ACCUM, 1);
        cudaEventRecord(eG2, 0);

        // ---- st1: l1 (fused intra gather) -> tmp ----
        GEMM_FULL(st1, h, nullptr, w0 + 1, lb1 + l * Hdim, nullptr, nullptr,
                  nullptr, nullptr, nullptr, nullptr, nullptr, nullptr, nullptr,
                  irp, ipk, bond_table,
                  tmp, SKn, (long)Hdim, FLAG_RELU | FLAG_PACKOUT, 0, 1);

        // ---- st1: l2 + fused combine ----
        cudaStreamWaitEvent(st1, eS2, 0);
        cudaStreamWaitEvent(st1, eG2, 0);
        GEMM_FULL(st1, tmp, nullptr, w0 + 2, lb2 + l * Hdim,
                  lbn_g + l * Hdim, lbn_b + l * Hdim, acc, yvv, ykk,
                  node_ids, sub_batch, xsum, xvvc,
                  nullptr, nullptr, nullptr,
                  h, SKn, (long)Hdim, FLAG_COMBINE, 1, 0);
        cudaEventRecord(eS1, st1);
        cudaStreamWaitEvent(0, eS1, 0);
    }

    // ---- epilogue ----
    cudaMemsetAsync(d_out, 0, (size_t)out_size * sizeof(float));
    pool_kernel<<<CDIV(Nn * 32, TB), TB>>>(xsum, cnt, batch, (float*)d_out, Nn);
#undef GEMM_FULL
#undef GEMM_S
}

// round 16
// speedup vs baseline: 1.1467x; 1.1467x over previous
#include <cuda_runtime.h>
#include <cuda_bf16.h>
#include <cstdint>

#define Hdim 128
#define KSUB 16
#define SK_C 128000
#define N_C  60000
#define S_C  8000
#define L_C  3
#define EI_C 512000
#define EG_C 960000
#define HH   (Hdim * Hdim)

#define FLAG_RELU    1
#define FLAG_ACCUM   2
#define FLAG_PACKOUT 4
#define FLAG_COMBINE 8

#define CDIV(a, b) (((a) + (b) - 1) / (b))

// ------------------------- scratch -------------------------
__device__ float g_h[SK_C * Hdim];      // packed bf16 hi|lo
__device__ float g_acc[SK_C * Hdim];
__device__ float g_agg[SK_C * Hdim];    // packed (h+agg)
__device__ float g_tmp[SK_C * Hdim];    // packed
__device__ float g_xsum[N_C * Hdim];
__device__ float g_aggN[N_C * Hdim];    // packed (xsum/cnt + aggN)
__device__ float g_tmpN[N_C * Hdim];    // packed
__device__ float g_yvv[N_C * Hdim];
__device__ float g_xvvc[N_C * Hdim];
__device__ float g_ykk[S_C * Hdim];
__device__ int   g_cnt[N_C];
__device__ int   g_rcnt[N_C];
__device__ unsigned char g_wbf[L_C * 7 * 65536];

// CSR scratch
__device__ int g_irp[SK_C + 1];
__device__ int g_ipk[EI_C];
__device__ int g_ideg[SK_C];
__device__ int g_ibs[512];
__device__ int g_grp[N_C + 1];
__device__ int g_gpk[EG_C];
__device__ int g_gdeg[N_C];
__device__ int g_gbs[512];

// ------------------------- helpers -------------------------
__device__ __forceinline__ uint32_t smem_u32(const void* p) {
    uint32_t a;
    asm("{ .reg .u64 t; cvta.to.shared.u64 t, %1; cvt.u32.u64 %0, t; }" : "=r"(a) : "l"(p));
    return a;
}
__device__ __forceinline__ void ldsm4(uint32_t* r, uint32_t addr) {
    asm volatile("ldmatrix.sync.aligned.m8n8.x4.shared.b16 {%0,%1,%2,%3}, [%4];"
        : "=r"(r[0]), "=r"(r[1]), "=r"(r[2]), "=r"(r[3]) : "r"(addr));
}
__device__ __forceinline__ void mma16816(float* c, const uint32_t* a, uint32_t b0, uint32_t b1) {
    asm volatile("mma.sync.aligned.m16n8k16.row.col.f32.bf16.bf16.f32 "
        "{%0,%1,%2,%3}, {%4,%5,%6,%7}, {%8,%9}, {%0,%1,%2,%3};"
        : "+f"(c[0]), "+f"(c[1]), "+f"(c[2]), "+f"(c[3])
        : "r"(a[0]), "r"(a[1]), "r"(a[2]), "r"(a[3]), "r"(b0), "r"(b1));
}
__device__ __forceinline__ uint32_t pack_bf16(float x, float y) {
    __nv_bfloat162 h = __float22bfloat162_rn(make_float2(x, y));
    return *(uint32_t*)&h;
}
__device__ __forceinline__ uint32_t split_pack(float x) {
    __nv_bfloat16 hb = __float2bfloat16_rn(x);
    float hf = __bfloat162float(hb);
    __nv_bfloat16 lb = __float2bfloat16_rn(x - hf);
    return (uint32_t)__bfloat16_as_ushort(hb) | ((uint32_t)__bfloat16_as_ushort(lb) << 16);
}
__device__ __forceinline__ float rec_pk(uint32_t p) {
    return __uint_as_float(p << 16) + __uint_as_float(p & 0xFFFF0000u);
}
__device__ __forceinline__ void red_v4(float* p, float x, float y, float z, float w) {
    asm volatile("red.global.add.v4.f32 [%0], {%1, %2, %3, %4};"
        :: "l"(p), "f"(x), "f"(y), "f"(z), "f"(w) : "memory");
}
__device__ __forceinline__ void red_v2(float* p, float x, float y) {
    asm volatile("red.global.add.v2.f32 [%0], {%1, %2};"
        :: "l"(p), "f"(x), "f"(y) : "memory");
}

// ------------------------- weight prep -------------------------
__global__ void prep_weights(const float* __restrict__ s0, const float* __restrict__ s1,
                             const float* __restrict__ s2, const float* __restrict__ s3,
                             const float* __restrict__ s4, const float* __restrict__ s5,
                             const float* __restrict__ s6, unsigned char* __restrict__ dst, int L)
{
    int i = blockIdx.x * blockDim.x + threadIdx.x;
    int total = L * 7 * HH;
    if (i >= total) return;
    int m = i >> 14;
    int r = i & (HH - 1);
    int o = r >> 7, k = r & 127;
    int l = m / 7, j = m % 7;
    const float* base;
    switch (j) {
        case 0: base = s0; break;
        case 1: base = s1; break;
        case 2: base = s2; break;
        case 3: base = s3; break;
        case 4: base = s4; break;
        case 5: base = s5; break;
        default: base = s6; break;
    }
    float v = base[(size_t)l * HH + o * Hdim + k];
    __nv_bfloat16 hb = __float2bfloat16_rn(v);
    float lo = v - __bfloat162float(hb);
    __nv_bfloat16 lb = __float2bfloat16_rn(lo);
    uint32_t off = (uint32_t)(o * 256 + (((k >> 3) ^ (o & 7)) * 16) + (k & 7) * 2);
    unsigned char* mb = dst + (size_t)m * 65536;
    *(unsigned short*)(mb + off)          = __bfloat16_as_ushort(hb);
    *(unsigned short*)(mb + 32768 + off)  = __bfloat16_as_ushort(lb);
}

// ------------------------- CSR build -------------------------
__global__ void hist_kernel(const int* __restrict__ dst, int* __restrict__ deg, int E)
{
    int e = blockIdx.x * blockDim.x + threadIdx.x;
    if (e < E) atomicAdd(&deg[dst[e]], 1);
}

__global__ void scan_part(const int* __restrict__ deg, int* __restrict__ rowptr,
                          int* __restrict__ bsum, int n)
{
    __shared__ int s[256];
    int i = blockIdx.x * 256 + threadIdx.x;
    int v = (i < n) ? deg[i] : 0;
    s[threadIdx.x] = v;
    __syncthreads();
#pragma unroll
    for (int off = 1; off < 256; off <<= 1) {
        int t = (threadIdx.x >= off) ? s[threadIdx.x - off] : 0;
        __syncthreads();
        s[threadIdx.x] += t;
        __syncthreads();
    }
    if (i < n) rowptr[i] = s[threadIdx.x] - v;
    if (threadIdx.x == 255) bsum[blockIdx.x] = s[255];
}

__global__ void scan_top(int* __restrict__ bsum, int B)
{
    __shared__ int s[512];
    int v = (threadIdx.x < B) ? bsum[threadIdx.x] : 0;
    s[threadIdx.x] = v;
    __syncthreads();
#pragma unroll
    for (int off = 1; off < 512; off <<= 1) {
        int t = (threadIdx.x >= off) ? s[threadIdx.x - off] : 0;
        __syncthreads();
        s[threadIdx.x] += t;
        __syncthreads();
    }
    if (threadIdx.x < B) bsum[threadIdx.x] = s[threadIdx.x] - v;
}

__global__ void scan_add(int* __restrict__ rowptr, const int* __restrict__ bsum, int n, int E)
{
    int i = blockIdx.x * blockDim.x + threadIdx.x;
    if (i < n) rowptr[i] += bsum[i >> 8];
    if (i == n) rowptr[n] = E;
}

__global__ void csr_scatter(const int* __restrict__ src, const int* __restrict__ dst,
                            const int* __restrict__ bid, int* __restrict__ cursor,
                            int* __restrict__ packed, int E)
{
    int e = blockIdx.x * blockDim.x + threadIdx.x;
    if (e >= E) return;
    int d = dst[e];
    int pos = atomicAdd(&cursor[d], 1);
    packed[pos] = src[e] | (bid[e] << 25);
}

// ------------------------- fused gather: out[w] = split_pack(own + sum relu(...)) -------------------------
__global__ void gather_msg(const float* __restrict__ xin, const int* __restrict__ rowptr,
                           const int* __restrict__ packed, const int* __restrict__ cnt,
                           const float* __restrict__ bond, float* __restrict__ aggOut,
                           int Nn, int inFmt)
{
    int w = (blockIdx.x * blockDim.x + threadIdx.x) >> 5;
    int l = threadIdx.x & 31;
    if (w >= Nn) return;
    int beg = __ldg(rowptr + w), end = __ldg(rowptr + w + 1);
    float4 acc;
    if (inFmt) {
        uint4 pk = *(const uint4*)((const uint32_t*)xin + (size_t)w * Hdim + l * 4);
        acc.x = rec_pk(pk.x); acc.y = rec_pk(pk.y);
        acc.z = rec_pk(pk.z); acc.w = rec_pk(pk.w);
    } else {
        acc = *(const float4*)(xin + (size_t)w * Hdim + l * 4);
        if (cnt) {
            float invw = 1.f / (float)max(__ldg(cnt + w), 1);
            acc.x *= invw; acc.y *= invw; acc.z *= invw; acc.w *= invw;
        }
    }
#pragma unroll 2
    for (int e = beg; e < end; e++) {
        uint32_t p = (uint32_t)__ldg(packed + e);
        int s = (int)(p & 0x1FFFFFFu);
        int b = (int)(p >> 25);
        float inv = 1.f;
        if (cnt) inv = 1.f / (float)max(__ldg(cnt + s), 1);
        float4 hv;
        if (inFmt) {
            uint4 pk = *(const uint4*)((const uint32_t*)xin + (size_t)s * Hdim + l * 4);
            hv.x = rec_pk(pk.x); hv.y = rec_pk(pk.y);
            hv.z = rec_pk(pk.z); hv.w = rec_pk(pk.w);
        } else {
            hv = *(const float4*)(xin + (size_t)s * Hdim + l * 4);
        }
        float4 bv = *(const float4*)(bond + (size_t)b * Hdim + l * 4);
        acc.x += fmaxf(hv.x * inv + bv.x, 0.f);
        acc.y += fmaxf(hv.y * inv + bv.y, 0.f);
        acc.z += fmaxf(hv.z * inv + bv.z, 0.f);
        acc.w += fmaxf(hv.w * inv + bv.w, 0.f);
    }
    uint4 pk = make_uint4(split_pack(acc.x), split_pack(acc.y),
                          split_pack(acc.z), split_pack(acc.w));
    *(uint4*)((uint32_t*)aggOut + (size_t)w * Hdim + l * 4) = pk;
}

// ------------------------- tensor-core GEMM (+combine epilogue) -------------------------
#define SMEM_DYN 196608

__global__ __launch_bounds__(512)
void gemm_mma(const float* __restrict__ X1, const float* __restrict__ X2,
              const int* __restrict__ rowScale,
              const unsigned char* __restrict__ WB, const float* __restrict__ bias,
              const float* __restrict__ gamma, const float* __restrict__ beta,
              const float* __restrict__ accIn, const float* __restrict__ yvv,
              const float* __restrict__ ykk,
              const int* __restrict__ node_ids, const int* __restrict__ sub_batch,
              float* __restrict__ xsum, float* __restrict__ xvvc,
              float* __restrict__ Y, int M, long inStride, int flags, int inFmt)
{
    extern __shared__ char sm[];
    const uint32_t sbase = smem_u32(sm);
    const int tid = threadIdx.x;
    const long m0 = (long)blockIdx.x * 256;

    {
        const float4* wsrc = (const float4*)WB;
        float4* wdst = (float4*)(sm + 131072);
#pragma unroll
        for (int i = 0; i < 8; i++)
            wdst[tid + i * 512] = wsrc[tid + i * 512];
    }

    if (inFmt && !X2 && !rowScale) {
#pragma unroll
        for (int i = 0; i < 8; i++) {
            int g = tid + i * 512;
            int row = g >> 4, chunk = g & 15;
            long m = m0 + row;
            uint4 pa = make_uint4(0, 0, 0, 0), pb = make_uint4(0, 0, 0, 0);
            if (m < M) {
                const uint4* xp = (const uint4*)((const uint32_t*)X1 + m * inStride + chunk * 8);
                pa = xp[0];
                pb = xp[1];
            }
            uint4 hi, lo;
            hi.x = __byte_perm(pa.x, pa.y, 0x5410);
            hi.y = __byte_perm(pa.z, pa.w, 0x5410);
            hi.z = __byte_perm(pb.x, pb.y, 0x5410);
            hi.w = __byte_perm(pb.z, pb.w, 0x5410);
            lo.x = __byte_perm(pa.x, pa.y, 0x7632);
            lo.y = __byte_perm(pa.z, pa.w, 0x7632);
            lo.z = __byte_perm(pb.x, pb.y, 0x7632);
            lo.w = __byte_perm(pb.z, pb.w, 0x7632);
            uint32_t off = (uint32_t)(row * 256 + ((chunk ^ (row & 7)) * 16));
            *(uint4*)(sm + off)         = hi;
            *(uint4*)(sm + 65536 + off) = lo;
        }
    } else {
#pragma unroll
        for (int i = 0; i < 8; i++) {
            int g = tid + i * 512;
            int row = g >> 4, chunk = g & 15;
            long m = m0 + row;
            float v[8];
#pragma unroll
            for (int q = 0; q < 8; q++) v[q] = 0.f;
            if (m < M) {
                if (inFmt) {
                    const uint4* xp = (const uint4*)((const uint32_t*)X1 + m * inStride + chunk * 8);
                    uint4 pa = xp[0], pb = xp[1];
                    v[0] = rec_pk(pa.x); v[1] = rec_pk(pa.y);
                    v[2] = rec_pk(pa.z); v[3] = rec_pk(pa.w);
                    v[4] = rec_pk(pb.x); v[5] = rec_pk(pb.y);
                    v[6] = rec_pk(pb.z); v[7] = rec_pk(pb.w);
                } else {
                    const float* xp = X1 + m * inStride + chunk * 8;
                    float4 a = *(const float4*)xp;
                    float4 b = *(const float4*)(xp + 4);
                    v[0] = a.x; v[1] = a.y; v[2] = a.z; v[3] = a.w;
                    v[4] = b.x; v[5] = b.y; v[6] = b.z; v[7] = b.w;
                }
                if (rowScale) {
                    float inv = 1.f / (float)max(__ldg(rowScale + m), 1);
#pragma unroll
                    for (int q = 0; q < 8; q++) v[q] *= inv;
                }
                if (X2) {
                    const float* yp2 = X2 + m * (long)Hdim + chunk * 8;
                    float4 c = *(const float4*)yp2;
                    float4 d = *(const float4*)(yp2 + 4);
                    v[0] += c.x; v[1] += c.y; v[2] += c.z; v[3] += c.w;
                    v[4] += d.x; v[5] += d.y; v[6] += d.z; v[7] += d.w;
                }
            }
            uint32_t hp[4], lp[4];
#pragma unroll
            for (int q = 0; q < 4; q++) {
                float x = v[q * 2], y = v[q * 2 + 1];
                uint32_t hh = pack_bf16(x, y);
                __nv_bfloat162 hv = *(__nv_bfloat162*)&hh;
                float lx = x - __bfloat162float(hv.x);
                float ly = y - __bfloat162float(hv.y);
                hp[q] = hh;
                lp[q] = pack_bf16(lx, ly);
            }
            uint32_t off = (uint32_t)(row * 256 + ((chunk ^ (row & 7)) * 16));
            *(uint4*)(sm + off)         = make_uint4(hp[0], hp[1], hp[2], hp[3]);
            *(uint4*)(sm + 65536 + off) = make_uint4(lp[0], lp[1], lp[2], lp[3]);
        }
    }
    __syncthreads();

    const int wid = tid >> 5, lane = tid & 31;
    const int rw = (wid & 7) * 32;
    const int cw = (wid >> 3) * 64;
    const int lg = lane >> 3, lr = lane & 7;

    float c[2][8][4];
#pragma unroll
    for (int mt = 0; mt < 2; mt++)
#pragma unroll
        for (int nt = 0; nt < 8; nt++)
#pragma unroll
            for (int q = 0; q < 4; q++) c[mt][nt][q] = 0.f;

    const int aRow0 = rw + (lg & 1) * 8 + lr;
    const int bN0   = cw + (lg >> 1) * 8 + lr;

#pragma unroll 1
    for (int ks = 0; ks < 8; ks++) {
        const int kcA = ks * 2 + (lg >> 1);
        const int kcB = ks * 2 + (lg & 1);
        uint32_t ah[2][4], al[2][4];
#pragma unroll
        for (int mt = 0; mt < 2; mt++) {
            int row = aRow0 + mt * 16;
            uint32_t addr = sbase + row * 256 + ((kcA ^ (row & 7)) * 16);
            ldsm4(ah[mt], addr);
            ldsm4(al[mt], addr + 65536);
        }
#pragma unroll
        for (int ng = 0; ng < 4; ng++) {
            int n = bN0 + ng * 16;
            uint32_t baddr = sbase + 131072 + n * 256 + ((kcB ^ (n & 7)) * 16);
            uint32_t bh[4], bl[4];
            ldsm4(bh, baddr);
            ldsm4(bl, baddr + 32768);
#pragma unroll
            for (int mt = 0; mt < 2; mt++) {
#pragma unroll
                for (int half = 0; half < 2; half++) {
                    int nt = ng * 2 + half;
                    mma16816(c[mt][nt], ah[mt], bh[half * 2], bh[half * 2 + 1]);
                    mma16816(c[mt][nt], ah[mt], bl[half * 2], bl[half * 2 + 1]);
                    mma16816(c[mt][nt], al[mt], bh[half * 2], bh[half * 2 + 1]);
                }
            }
        }
    }

    {
        const int ncol0 = cw + (lane & 3) * 2;
        float2 bi[8], ga[8], be[8];
#pragma unroll
        for (int nt = 0; nt < 8; nt++) {
            bi[nt] = *(const float2*)(bias + ncol0 + nt * 8);
            if (gamma) {
                ga[nt] = *(const float2*)(gamma + ncol0 + nt * 8);
                be[nt] = *(const float2*)(beta  + ncol0 + nt * 8);
            }
        }
#pragma unroll
        for (int mt = 0; mt < 2; mt++) {
#pragma unroll
            for (int h = 0; h < 2; h++) {
                long m = m0 + rw + mt * 16 + h * 8 + (lane >> 2);
                if (m >= M) continue;
                if (flags & FLAG_COMBINE) {
                    uint32_t* hrow = (uint32_t*)Y + m * (long)Hdim;
                    int nid = __ldg(node_ids + m);
                    if (nid < 0) {
#pragma unroll
                        for (int nt = 0; nt < 8; nt++)
                            *(uint2*)(hrow + ncol0 + nt * 8) = make_uint2(0u, 0u);
                    } else {
                        int sb = __ldg(sub_batch + m);
                        const float* arow = accIn + m * (long)Hdim;
                        const float* vrow = yvv + (size_t)nid * Hdim;
                        const float* krow = ykk + (size_t)sb * Hdim;
                        float* xsrow = xsum + (size_t)nid * Hdim;
                        float* xvrow = xvvc + (size_t)nid * Hdim;
                        bool isRoot = ((m & (KSUB - 1)) == 0);
#pragma unroll
                        for (int nt = 0; nt < 8; nt++) {
                            int col = ncol0 + nt * 8;
                            float x = c[mt][nt][h * 2 + 0] + bi[nt].x;
                            float y = c[mt][nt][h * 2 + 1] + bi[nt].y;
                            x = x * ga[nt].x + be[nt].x;
                            y = y * ga[nt].y + be[nt].y;
                            float2 av = *(const float2*)(arow + col);
                            float2 vv = *(const float2*)(vrow + col);
                            float2 kv = *(const float2*)(krow + col);
                            x = fmaxf(x + av.x + vv.x + kv.x, 0.f);
                            y = fmaxf(y + av.y + vv.y + kv.y, 0.f);
                            *(uint2*)(hrow + col) = make_uint2(split_pack(x), split_pack(y));
                            red_v2(xsrow + col, x, y);
                            if (isRoot) red_v2(xvrow + col, x, y);
                        }
                    }
                } else {
                    float* yrow = Y + m * (long)Hdim;
#pragma unroll
                    for (int nt = 0; nt < 8; nt++) {
                        int col = ncol0 + nt * 8;
                        float x = c[mt][nt][h * 2 + 0] + bi[nt].x;
                        float y = c[mt][nt][h * 2 + 1] + bi[nt].y;
                        if (gamma) {
                            x = x * ga[nt].x + be[nt].x;
                            y = y * ga[nt].y + be[nt].y;
                        }
                        if (flags & FLAG_RELU) { x = fmaxf(x, 0.f); y = fmaxf(y, 0.f); }
                        if (flags & FLAG_ACCUM) {
                            float2 old = *(float2*)(yrow + col);
                            x += old.x; y += old.y;
                        }
                        if (flags & FLAG_PACKOUT) {
                            uint2 pk = make_uint2(split_pack(x), split_pack(y));
                            *(uint2*)((uint32_t*)yrow + col) = pk;
                        } else {
                            *(float2*)(yrow + col) = make_float2(x, y);
                        }
                    }
                }
            }
        }
    }
}

// ------------------------- counts -------------------------
__global__ void count_kernel(const int* __restrict__ node_ids, int* __restrict__ cnt, int SKn)
{
    int i = blockIdx.x * blockDim.x + threadIdx.x;
    if (i >= SKn) return;
    int nid = node_ids[i];
    if (nid >= 0) atomicAdd(&cnt[nid], 1);
}
__global__ void rcount_kernel(const int* __restrict__ node_ids, int* __restrict__ rcnt, int Sn)
{
    int s = blockIdx.x * blockDim.x + threadIdx.x;
    if (s >= Sn) return;
    int nid = node_ids[s * KSUB];
    if (nid >= 0) atomicAdd(&rcnt[nid], 1);
}

// ------------------------- init h -------------------------
__global__ void init_h(const float* __restrict__ atom_table, const float* __restrict__ role_table,
                       const int* __restrict__ atom_ids, const int* __restrict__ node_ids,
                       float* __restrict__ h, float* __restrict__ xsum, float* __restrict__ xvvc,
                       int SKn)
{
    int t = blockIdx.x * blockDim.x + threadIdx.x;
    int row = t >> 5;
    if (row >= SKn) return;
    int q = t & 31;
    int nid = node_ids[row];
    float4 out = make_float4(0.f, 0.f, 0.f, 0.f);
    if (nid >= 0) {
        int aid = atom_ids[row];
        float4 v = *(const float4*)(atom_table + (size_t)aid * Hdim + q * 4);
        const float* role = role_table + (((row & (KSUB - 1)) == 0) ? Hdim : 0);
        float4 r = *(const float4*)(role + q * 4);
        out = make_float4(v.x + r.x, v.y + r.y, v.z + r.z, v.w + r.w);
    }
    uint4 pk = make_uint4(split_pack(out.x), split_pack(out.y),
                          split_pack(out.z), split_pack(out.w));
    *(uint4*)((uint32_t*)h + (size_t)row * Hdim + q * 4) = pk;
    if (nid >= 0) {
        red_v4(xsum + (size_t)nid * Hdim + q * 4, out.x, out.y, out.z, out.w);
        if ((row & (KSUB - 1)) == 0)
            red_v4(xvvc + (size_t)nid * Hdim + q * 4, out.x, out.y, out.z, out.w);
    }
}

// ------------------------- final pool -------------------------
__global__ void pool_kernel(const float* __restrict__ xsum, const int* __restrict__ cnt,
                            const int* __restrict__ batch, float* __restrict__ out, int Nn)
{
    int t = blockIdx.x * blockDim.x + threadIdx.x;
    int n = t >> 5;
    if (n >= Nn) return;
    int q = t & 31;
    float inv = 1.f / (float)max(cnt[n], 1);
    int g = batch[n];
    float4 v = *(const float4*)(xsum + (size_t)n * Hdim + q * 4);
    red_v4(out + (size_t)g * Hdim + q * 4, v.x * inv, v.y * inv, v.z * inv, v.w * inv);
}

// ------------------------- host orchestration -------------------------
extern "C" void kernel_launch(void* const* d_in, const int* in_sizes, int n_in,
                              void* d_out, int out_size)
{
    const float* atom_table = (const float*)d_in[0];
    const float* bond_table = (const float*)d_in[1];
    const float* role_table = (const float*)d_in[2];
    const float* lW1  = (const float*)d_in[3];
    const float* lb1  = (const float*)d_in[4];
    const float* lW2  = (const float*)d_in[5];
    const float* lb2  = (const float*)d_in[6];
    const float* gW1  = (const float*)d_in[7];
    const float* gb1  = (const float*)d_in[8];
    const float* gW2  = (const float*)d_in[9];
    const float* gb2  = (const float*)d_in[10];
    const float* lbn_g = (const float*)d_in[11];
    const float* lbn_b = (const float*)d_in[12];
    const float* gbn_g = (const float*)d_in[13];
    const float* gbn_b = (const float*)d_in[14];
    const float* skipW = (const float*)d_in[15];
    const float* skipb = (const float*)d_in[16];
    const float* vvW  = (const float*)d_in[17];
    const float* vvb  = (const float*)d_in[18];
    const float* kkW  = (const float*)d_in[19];
    const float* kkb  = (const float*)d_in[20];
    const int* atom_ids  = (const int*)d_in[21];
    const int* bid_i     = (const int*)d_in[22];
    const int* bid_g     = (const int*)d_in[23];
    const int* intra_ei  = (const int*)d_in[24];
    const int* node_ids  = (const int*)d_in[25];
    const int* edge_index = (const int*)d_in[26];
    const int* sub_batch = (const int*)d_in[27];
    const int* batch     = (const int*)d_in[28];

    const int SKn = in_sizes[21];
    const int EIn = in_sizes[22];
    const int EGn = in_sizes[23];
    const int Nn  = in_sizes[28];
    const int Sn  = SKn / KSUB;
    const int L   = in_sizes[4] / Hdim;

    float *h, *acc, *agg, *tmp, *xsum, *aggN, *tmpN, *yvv, *xvvc, *ykk;
    int *cnt, *rcnt;
    int *irp, *ipk, *ideg, *ibs, *grp, *gpk, *gdeg, *gbs;
    unsigned char* wbf;
    cudaGetSymbolAddress((void**)&h,    g_h);
    cudaGetSymbolAddress((void**)&acc,  g_acc);
    cudaGetSymbolAddress((void**)&agg,  g_agg);
    cudaGetSymbolAddress((void**)&tmp,  g_tmp);
    cudaGetSymbolAddress((void**)&xsum, g_xsum);
    cudaGetSymbolAddress((void**)&aggN, g_aggN);
    cudaGetSymbolAddress((void**)&tmpN, g_tmpN);
    cudaGetSymbolAddress((void**)&yvv,  g_yvv);
    cudaGetSymbolAddress((void**)&xvvc, g_xvvc);
    cudaGetSymbolAddress((void**)&ykk,  g_ykk);
    cudaGetSymbolAddress((void**)&cnt,  g_cnt);
    cudaGetSymbolAddress((void**)&rcnt, g_rcnt);
    cudaGetSymbolAddress((void**)&wbf,  g_wbf);
    cudaGetSymbolAddress((void**)&irp,  g_irp);
    cudaGetSymbolAddress((void**)&ipk,  g_ipk);
    cudaGetSymbolAddress((void**)&ideg, g_ideg);
    cudaGetSymbolAddress((void**)&ibs,  g_ibs);
    cudaGetSymbolAddress((void**)&grp,  g_grp);
    cudaGetSymbolAddress((void**)&gpk,  g_gpk);
    cudaGetSymbolAddress((void**)&gdeg, g_gdeg);
    cudaGetSymbolAddress((void**)&gbs,  g_gbs);

    cudaFuncSetAttribute(gemm_mma, cudaFuncAttributeMaxDynamicSharedMemorySize, SMEM_DYN);

    static cudaStream_t st1 = nullptr, st2 = nullptr;
    static cudaEvent_t ev[24];
    if (!st1) {
        cudaStreamCreateWithFlags(&st1, cudaStreamNonBlocking);
        cudaStreamCreateWithFlags(&st2, cudaStreamNonBlocking);
        for (int i = 0; i < 24; i++)
            cudaEventCreateWithFlags(&ev[i], cudaEventDisableTiming);
    }

    const int TB = 256;
    const size_t nBytes = (size_t)Nn * Hdim * sizeof(float);

#define GEMM_F(stream, X1p, X2p, rsp, widx, biasp, gammap, betap, accp, yvvp, ykkp, nidp, sbp, xsp, xvp, Yp, Mv, strv, flg, fmt) \
    gemm_mma<<<CDIV((Mv), 256), 512, SMEM_DYN, (stream)>>>((X1p), (X2p), (rsp), \
        wbf + (size_t)(widx) * 65536, (biasp), (gammap), (betap), (accp), (yvvp), (ykkp), \
        (nidp), (sbp), (xsp), (xvp), (Yp), (Mv), (strv), (flg), (fmt))
#define GEMM_S(stream, X1p, X2p, rsp, widx, biasp, gammap, betap, Yp, Mv, strv, flg, fmt) \
    GEMM_F(stream, X1p, X2p, rsp, widx, biasp, gammap, betap, nullptr, nullptr, nullptr, \
           nullptr, nullptr, nullptr, nullptr, Yp, Mv, strv, flg, fmt)

    // ---- fork FIRST ----
    cudaEvent_t eStart = ev[21];
    cudaEventRecord(eStart, 0);
    cudaStreamWaitEvent(st1, eStart, 0);
    cudaStreamWaitEvent(st2, eStart, 0);

    // st1: intra CSR
    {
        int B = CDIV(SKn, 256);
        cudaMemsetAsync(ideg, 0, (size_t)SKn * sizeof(int), st1);
        hist_kernel<<<CDIV(EIn, TB), TB, 0, st1>>>(intra_ei + EIn, ideg, EIn);
        scan_part<<<B, 256, 0, st1>>>(ideg, irp, ibs, SKn);
        scan_top<<<1, 512, 0, st1>>>(ibs, B);
        scan_add<<<CDIV(SKn + 1, TB), TB, 0, st1>>>(irp, ibs, SKn, EIn);
        cudaMemcpyAsync(ideg, irp, (size_t)SKn * sizeof(int), cudaMemcpyDeviceToDevice, st1);
        csr_scatter<<<CDIV(EIn, TB), TB, 0, st1>>>(intra_ei, intra_ei + EIn, bid_i, ideg, ipk, EIn);
    }
    // st2: global CSR
    {
        int B = CDIV(Nn, 256);
        cudaMemsetAsync(gdeg, 0, (size_t)Nn * sizeof(int), st2);
        hist_kernel<<<CDIV(EGn, TB), TB, 0, st2>>>(edge_index + EGn, gdeg, EGn);
        scan_part<<<B, 256, 0, st2>>>(gdeg, grp, gbs, Nn);
        scan_top<<<1, 512, 0, st2>>>(gbs, B);
        scan_add<<<CDIV(Nn + 1, TB), TB, 0, st2>>>(grp, gbs, Nn, EGn);
        cudaMemcpyAsync(gdeg, grp, (size_t)Nn * sizeof(int), cudaMemcpyDeviceToDevice, st2);
        csr_scatter<<<CDIV(EGn, TB), TB, 0, st2>>>(edge_index, edge_index + EGn, bid_g, gdeg, gpk, EGn);
    }
    cudaEvent_t eCsr2 = ev[22];
    cudaEventRecord(eCsr2, st2);
    cudaStreamWaitEvent(0, eCsr2, 0);

    // stream 0: weights, counts, init
    prep_weights<<<CDIV(L * 7 * HH, TB), TB>>>(skipW, lW1, lW2, gW1, gW2, vvW, kkW, wbf, L);
    cudaMemsetAsync(cnt,  0, (size_t)Nn * sizeof(int));
    cudaMemsetAsync(rcnt, 0, (size_t)Nn * sizeof(int));
    count_kernel<<<CDIV(SKn, TB), TB>>>(node_ids, cnt, SKn);
    rcount_kernel<<<CDIV(Sn, TB), TB>>>(node_ids, rcnt, Sn);
    cudaMemsetAsync(xsum, 0, nBytes);
    cudaMemsetAsync(xvvc, 0, nBytes);
    init_h<<<CDIV(SKn * 32, TB), TB>>>(atom_table, role_table, atom_ids, node_ids,
                                       h, xsum, xvvc, SKn);

    for (int l = 0; l < L; l++) {
        const int w0 = l * 7;
        cudaEvent_t eFork = ev[l * 7 + 0];
        cudaEvent_t eS1   = ev[l * 7 + 1];
        cudaEvent_t eS2   = ev[l * 7 + 2];
        cudaEvent_t eVV   = ev[l * 7 + 3];
        cudaEvent_t eSkip = ev[l * 7 + 4];
        cudaEvent_t eG1   = ev[l * 7 + 5];
        cudaEvent_t eG2   = ev[l * 7 + 6];

        cudaEventRecord(eFork, 0);
        cudaStreamWaitEvent(st1, eFork, 0);
        cudaStreamWaitEvent(st2, eFork, 0);

        // ---- st2: skip -> acc ; vv -> yvv ; kk -> ykk ----
        GEMM_S(st2, h, nullptr, nullptr, w0 + 0, skipb + l * Hdim,
               nullptr, nullptr, acc, SKn, (long)Hdim, 0, 1);
        cudaEventRecord(eSkip, st2);
        GEMM_S(st2, xvvc, nullptr, rcnt, w0 + 5, vvb + l * Hdim,
               nullptr, nullptr, yvv, Nn, (long)Hdim, 0, 0);
        cudaEventRecord(eVV, st2);
        GEMM_S(st2, h, nullptr, nullptr, w0 + 6, kkb + l * Hdim,
               nullptr, nullptr, ykk, Sn, (long)KSUB * Hdim, 0, 1);

        // ---- st1: fused intra gather -> agg ; l1 -> tmp ----
        gather_msg<<<CDIV(SKn * 32, TB), TB, 0, st1>>>(h, irp, ipk, nullptr, bond_table,
                                                       agg, SKn, 1);
        GEMM_S(st1, agg, nullptr, nullptr, w0 + 1, lb1 + l * Hdim,
               nullptr, nullptr, tmp, SKn, (long)Hdim, FLAG_RELU | FLAG_PACKOUT, 1);

        // ---- stream 0: fused global gather -> aggN ; g1 ; g2 (memsets moved to st2) ----
        gather_msg<<<CDIV(Nn * 32, TB), TB>>>(xsum, grp, gpk, cnt, bond_table, aggN, Nn, 0);
        GEMM_S(0, aggN, nullptr, nullptr, w0 + 3, gb1 + l * Hdim,
               nullptr, nullptr, tmpN, Nn, (long)Hdim, FLAG_RELU | FLAG_PACKOUT, 1);
        cudaEventRecord(eG1, 0);   // xsum fully consumed (gatherN ordered before on stream 0)
        cudaStreamWaitEvent(0, eVV, 0);
        GEMM_S(0, tmpN, nullptr, nullptr, w0 + 4, gb2 + l * Hdim,
               gbn_g + l * Hdim, gbn_b + l * Hdim, yvv, Nn, (long)Hdim, FLAG_ACCUM, 1);
        cudaEventRecord(eG2, 0);

        // ---- st2 (tail): zero xsum/xvvc once g1 consumed xsum (vv consumed xvvc on st2) ----
        cudaStreamWaitEvent(st2, eG1, 0);
        cudaMemsetAsync(xsum, 0, nBytes, st2);
        cudaMemsetAsync(xvvc, 0, nBytes, st2);
        cudaEventRecord(eS2, st2);

        // ---- st1: l2 + fused combine -> h (packed), scatters xsum/xvvc ----
        cudaStreamWaitEvent(st1, eSkip, 0);
        cudaStreamWaitEvent(st1, eS2, 0);
        cudaStreamWaitEvent(st1, eG2, 0);
        GEMM_F(st1, tmp, nullptr, nullptr, w0 + 2, lb2 + l * Hdim,
               lbn_g + l * Hdim, lbn_b + l * Hdim, acc, yvv, ykk,
               node_ids, sub_batch, xsum, xvvc,
               h, SKn, (long)Hdim, FLAG_COMBINE, 1);
        cudaEventRecord(eS1, st1);
        cudaStreamWaitEvent(0, eS1, 0);
    }

    // ---- epilogue ----
    cudaMemsetAsync(d_out, 0, (size_t)out_size * sizeof(float));
    pool_kernel<<<CDIV(Nn * 32, TB), TB>>>(xsum, cnt, batch, (float*)d_out, Nn);
#undef GEMM_F
#undef GEMM_S
}